// round 5
// baseline (speedup 1.0000x reference)
#include <cuda_runtime.h>

#define BQ   4096
#define TT   1024
#define DD   3
#define HH   64
#define NBP  6       // batch pairs per block
#define BLK  128

typedef unsigned long long ull;

// Transposed/packed W_hh: WQ[(g*16 + kc)*64 + j] = float4 of W_hh[g*64+j][4kc..4kc+3]
// 3*16*64 float4 = 49152 bytes. Written by prep kernel each launch.
__device__ ulonglong2 WQ[3 * 16 * 64];

__device__ __forceinline__ ull fma2(ull a, ull b, ull c) {
    ull d;
    asm("fma.rn.f32x2 %0, %1, %2, %3;" : "=l"(d) : "l"(a), "l"(b), "l"(c));
    return d;
}
__device__ __forceinline__ float2 upk(ull a) {
    float2 v;
    asm("mov.b64 {%0, %1}, %2;" : "=f"(v.x), "=f"(v.y) : "l"(a));
    return v;
}
__device__ __forceinline__ float sigf(float x) {
    return __fdividef(1.0f, 1.0f + __expf(-x));
}
__device__ __forceinline__ float tanh_f(float x) {
    return __fdividef(2.0f, 1.0f + __expf(-2.0f * x)) - 1.0f;
}

__global__ void prep_kernel(const float* __restrict__ Whh) {
    int i = blockIdx.x * blockDim.x + threadIdx.x;
    if (i < 3 * 16 * 64) {
        int g  = i >> 10;
        int rem = i & 1023;
        int kc = rem >> 6;
        int j  = rem & 63;
        const float* src = Whh + (g * 64 + j) * 64 + kc * 4;
        float4 v = make_float4(src[0], src[1], src[2], src[3]);
        WQ[i] = *(const ulonglong2*)&v;
    }
}

// smem (floats): hbuf 2*12*64 = 1536, dif 6*64 = 384, hid 32*6 = 192
#define SM_H     (2 * 2 * NBP * 64)
#define SM_DIF   (NBP * 64)
#define SM_HID   (32 * NBP)
#define SMEM_FLOATS (SM_H + SM_DIF + SM_HID)
#define SMEM_BYTES  (SMEM_FLOATS * 4)

__global__ void __launch_bounds__(BLK, 5) siamese_gru_kernel(
    const float* __restrict__ x1, const float* __restrict__ x2,
    const float* __restrict__ Wih,
    const float* __restrict__ bih, const float* __restrict__ bhh,
    const float* __restrict__ W1,  const float* __restrict__ b1,
    const float* __restrict__ W2,  const float* __restrict__ b2,
    float* __restrict__ out)
{
    extern __shared__ float smem[];
    float* hbuf = smem;
    float* dif  = hbuf + SM_H;
    float* hid  = dif + SM_DIF;

    const int tid = threadIdx.x;
    const int j   = tid & 63;   // hidden unit
    const int q   = tid >> 6;   // branch: 0 -> x1, 1 -> x2
    const int bb  = blockIdx.x * NBP;

    // zero h buffer 0
    for (int i = tid; i < 2 * NBP * 64; i += BLK) hbuf[i] = 0.0f;

    // per-thread input weights/biases (unit j) in registers
    float wi[9];
#pragma unroll
    for (int g = 0; g < 3; g++)
#pragma unroll
        for (int d = 0; d < DD; d++)
            wi[g * 3 + d] = __ldg(Wih + (g * 64 + j) * DD + d);
    const float biasR  = __ldg(bih + j)       + __ldg(bhh + j);
    const float biasZ  = __ldg(bih + 64 + j)  + __ldg(bhh + 64 + j);
    const float biasN  = __ldg(bih + 128 + j);   // b_ih_n (outside r*)
    const float biasHN = __ldg(bhh + 128 + j);   // b_hh_n (inside r*)

    const float* xp = q ? x2 : x1;
    int xo[NBP];
#pragma unroll
    for (int s = 0; s < NBP; s++) {
        int b = bb + s;
        if (b > BQ - 1) b = BQ - 1;   // clamp OOB (duplicate work, guarded store)
        xo[s] = b * (TT * DD);
    }

    const ulonglong2* wqr = WQ + j;             // + kc*64
    const ulonglong2* wqz = WQ + 16 * 64 + j;
    const ulonglong2* wqn = WQ + 32 * 64 + j;

    float hold[NBP];
#pragma unroll
    for (int s = 0; s < NBP; s++) hold[s] = 0.0f;

    __syncthreads();

    int cur = 0;
#pragma unroll 1
    for (int t = 0; t < TT; t++) {
        const float* hc = hbuf + cur * (2 * NBP * 64) + (q * NBP) * 64;

        ull ar[NBP], az[NBP], an[NBP];
#pragma unroll
        for (int s = 0; s < NBP; s++) { ar[s] = 0ull; az[s] = 0ull; an[s] = 0ull; }

#pragma unroll
        for (int kc = 0; kc < 16; kc++) {
            ulonglong2 wr = __ldg(wqr + kc * 64);
            ulonglong2 wz = __ldg(wqz + kc * 64);
            ulonglong2 wn = __ldg(wqn + kc * 64);
#pragma unroll
            for (int s = 0; s < NBP; s++) {
                ulonglong2 hv = *(const ulonglong2*)(hc + s * 64 + kc * 4);
                ar[s] = fma2(wr.x, hv.x, ar[s]);
                ar[s] = fma2(wr.y, hv.y, ar[s]);
                az[s] = fma2(wz.x, hv.x, az[s]);
                az[s] = fma2(wz.y, hv.y, az[s]);
                an[s] = fma2(wn.x, hv.x, an[s]);
                an[s] = fma2(wn.y, hv.y, an[s]);
            }
        }

        float* hn_ = hbuf + (cur ^ 1) * (2 * NBP * 64) + (q * NBP) * 64;
        const float* xb = xp + t * DD;
#pragma unroll
        for (int s = 0; s < NBP; s++) {
            const float* xv = xb + xo[s];
            float xa = __ldg(xv), xd = __ldg(xv + 1), xc = __ldg(xv + 2);
            float xr = biasR + wi[0] * xa + wi[1] * xd + wi[2] * xc;
            float xz = biasZ + wi[3] * xa + wi[4] * xd + wi[5] * xc;
            float xn = biasN + wi[6] * xa + wi[7] * xd + wi[8] * xc;
            float2 vr = upk(ar[s]), vz = upk(az[s]), vn = upk(an[s]);
            float r = sigf(xr + vr.x + vr.y);
            float z = sigf(xz + vz.x + vz.y);
            float n = tanh_f(xn + r * (biasHN + vn.x + vn.y));
            float h = n + z * (hold[s] - n);
            hold[s] = h;
            hn_[s * 64 + j] = h;
        }
        __syncthreads();
        cur ^= 1;
    }

    // --- Siamese diff + MLP head, in-block ---
    const float* hf = hbuf + cur * (2 * NBP * 64);
    for (int i = tid; i < NBP * 64; i += BLK) {
        int s = i >> 6, k = i & 63;
        dif[i] = fabsf(hf[s * 64 + k] - hf[(NBP + s) * 64 + k]);
    }
    __syncthreads();

    if (tid < 32) {
        int m = tid;
        float acc[NBP];
        float bb1 = __ldg(b1 + m);
#pragma unroll
        for (int s = 0; s < NBP; s++) acc[s] = bb1;
        for (int k = 0; k < 64; k++) {
            float w = __ldg(W1 + m * 64 + k);
#pragma unroll
            for (int s = 0; s < NBP; s++) acc[s] += w * dif[s * 64 + k];
        }
#pragma unroll
        for (int s = 0; s < NBP; s++) hid[m * NBP + s] = fmaxf(acc[s], 0.0f);
    }
    __syncthreads();

    if (tid < NBP) {
        int gb = bb + tid;
        if (gb < BQ) {
            float a = __ldg(b2);
            for (int m = 0; m < 32; m++)
                a += __ldg(W2 + m) * hid[m * NBP + tid];
            out[gb] = sigf(a);
        }
    }
}

extern "C" void kernel_launch(void* const* d_in, const int* in_sizes, int n_in,
                              void* d_out, int out_size)
{
    const float* x1  = (const float*)d_in[0];
    const float* x2  = (const float*)d_in[1];
    const float* Wih = (const float*)d_in[2];
    const float* Whh = (const float*)d_in[3];
    const float* bih = (const float*)d_in[4];
    const float* bhh = (const float*)d_in[5];
    const float* W1  = (const float*)d_in[6];
    const float* b1  = (const float*)d_in[7];
    const float* W2  = (const float*)d_in[8];
    const float* b2  = (const float*)d_in[9];
    float* out = (float*)d_out;

    prep_kernel<<<12, 256>>>(Whh);

    int grid = (BQ + NBP - 1) / NBP;   // 683 blocks
    siamese_gru_kernel<<<grid, BLK, SMEM_BYTES>>>(
        x1, x2, Wih, bih, bhh, W1, b1, W2, b2, out);
}

// round 7
// speedup vs baseline: 1.8712x; 1.8712x over previous
#include <cuda_runtime.h>

#define BQ   4096
#define TT   1024
#define DD   3
#define NBP  14      // batch pairs per block
#define NST  7       // seqs handled per thread
#define PW   68      // W_hh shared pitch (floats): conflict-free LDS.128
#define BLK  256

typedef unsigned long long ull;

__device__ __forceinline__ ull fma2(ull a, ull b, ull c) {
    ull d;
    asm("fma.rn.f32x2 %0, %1, %2, %3;" : "=l"(d) : "l"(a), "l"(b), "l"(c));
    return d;
}
__device__ __forceinline__ float2 upk(ull a) {
    float2 v;
    asm("mov.b64 {%0, %1}, %2;" : "=f"(v.x), "=f"(v.y) : "l"(a));
    return v;
}
__device__ __forceinline__ float sigf(float x) {
    return __fdividef(1.0f, 1.0f + __expf(-x));
}
__device__ __forceinline__ float tanh_f(float x) {
    return __fdividef(2.0f, 1.0f + __expf(-2.0f * x)) - 1.0f;
}

// smem (floats): W 3*64*PW = 13056 ; hbuf 2*28*64 = 3584 ; dif 14*64 = 896 ; hid 32*14 = 448
#define SM_W     (3 * 64 * PW)
#define SM_H     (2 * 2 * NBP * 64)
#define SM_DIF   (NBP * 64)
#define SM_HID   (32 * NBP)
#define SMEM_FLOATS (SM_W + SM_H + SM_DIF + SM_HID)
#define SMEM_BYTES  (SMEM_FLOATS * 4)

__global__ void __launch_bounds__(BLK, 2) siamese_gru_kernel(
    const float* __restrict__ x1, const float* __restrict__ x2,
    const float* __restrict__ Wih, const float* __restrict__ Whh,
    const float* __restrict__ bih, const float* __restrict__ bhh,
    const float* __restrict__ W1,  const float* __restrict__ b1,
    const float* __restrict__ W2,  const float* __restrict__ b2,
    float* __restrict__ out)
{
    extern __shared__ float smem[];
    float* Wsh  = smem;
    float* hbuf = Wsh + SM_W;
    float* dif  = hbuf + SM_H;
    float* hid  = dif + SM_DIF;

    const int tid = threadIdx.x;
    const int j   = tid & 63;          // hidden unit
    const int q   = (tid >> 6) & 1;    // branch: 0 -> x1, 1 -> x2
    const int sh  = tid >> 7;          // s-half: 0 or 1
    const int bb  = blockIdx.x * NBP;
    const int sb  = sh * NST;          // first pair index of this thread

    // stage W_hh into shared: [g][row j][k], pitch PW
    for (int i = tid; i < 3 * 64 * 64; i += BLK) {
        int g = i >> 12, rem = i & 4095;
        int row = rem >> 6, k = rem & 63;
        Wsh[(g * 64 + row) * PW + k] = Whh[i];
    }
    // zero h buffer 0
    for (int i = tid; i < 2 * NBP * 64; i += BLK) hbuf[i] = 0.0f;

    // per-thread input weights/biases (unit j) in registers
    float wi[9];
#pragma unroll
    for (int g = 0; g < 3; g++)
#pragma unroll
        for (int d = 0; d < DD; d++)
            wi[g * 3 + d] = __ldg(Wih + (g * 64 + j) * DD + d);
    const float biasR  = __ldg(bih + j)       + __ldg(bhh + j);
    const float biasZ  = __ldg(bih + 64 + j)  + __ldg(bhh + 64 + j);
    const float biasN  = __ldg(bih + 128 + j);   // b_ih_n (outside r*)
    const float biasHN = __ldg(bhh + 128 + j);   // b_hh_n (inside r*)

    const float* xp = q ? x2 : x1;
    int xo[NST];
#pragma unroll
    for (int s = 0; s < NST; s++) {
        int b = bb + sb + s;
        if (b > BQ - 1) b = BQ - 1;   // clamp OOB (duplicate work, guarded store)
        xo[s] = b * (TT * DD);
    }

    const float* Wr = Wsh + (0 * 64 + j) * PW;
    const float* Wz = Wsh + (1 * 64 + j) * PW;
    const float* Wn = Wsh + (2 * 64 + j) * PW;

    float hold[NST];
    float xf[NST][3];
#pragma unroll
    for (int s = 0; s < NST; s++) {
        hold[s] = 0.0f;
        xf[s][0] = __ldg(xp + xo[s]);
        xf[s][1] = __ldg(xp + xo[s] + 1);
        xf[s][2] = __ldg(xp + xo[s] + 2);
    }

    __syncthreads();

    int cur = 0;
#pragma unroll 1
    for (int t = 0; t < TT; t++) {
        const float* hc = hbuf + cur * (2 * NBP * 64) + (q * NBP + sb) * 64;

        ull ar[NST], az[NST], an[NST];
#pragma unroll
        for (int s = 0; s < NST; s++) { ar[s] = 0ull; az[s] = 0ull; an[s] = 0ull; }

#pragma unroll
        for (int kk = 0; kk < 64; kk += 4) {
            ulonglong2 wr = *(const ulonglong2*)(Wr + kk);
            ulonglong2 wz = *(const ulonglong2*)(Wz + kk);
            ulonglong2 wn = *(const ulonglong2*)(Wn + kk);
#pragma unroll
            for (int s = 0; s < NST; s++) {
                ulonglong2 hv = *(const ulonglong2*)(hc + s * 64 + kk);
                ar[s] = fma2(wr.x, hv.x, ar[s]);
                ar[s] = fma2(wr.y, hv.y, ar[s]);
                az[s] = fma2(wz.x, hv.x, az[s]);
                az[s] = fma2(wz.y, hv.y, az[s]);
                an[s] = fma2(wn.x, hv.x, an[s]);
                an[s] = fma2(wn.y, hv.y, an[s]);
            }
        }

        float* hn_ = hbuf + (cur ^ 1) * (2 * NBP * 64) + (q * NBP + sb) * 64;
#pragma unroll
        for (int s = 0; s < NST; s++) {
            float xa = xf[s][0], xd = xf[s][1], xc = xf[s][2];
            float xr = biasR + wi[0] * xa + wi[1] * xd + wi[2] * xc;
            float xz = biasZ + wi[3] * xa + wi[4] * xd + wi[5] * xc;
            float xn = biasN + wi[6] * xa + wi[7] * xd + wi[8] * xc;
            float2 vr = upk(ar[s]), vz = upk(az[s]), vn = upk(an[s]);
            float r = sigf(xr + vr.x + vr.y);
            float z = sigf(xz + vz.x + vz.y);
            float n = tanh_f(xn + r * (biasHN + vn.x + vn.y));
            float h = n + z * (hold[s] - n);
            hold[s] = h;
            hn_[s * 64 + j] = h;
        }
        // prefetch x for t+1 (consumed after next GEMV -> latency hidden)
        if (t + 1 < TT) {
            const float* xb = xp + (t + 1) * DD;
#pragma unroll
            for (int s = 0; s < NST; s++) {
                xf[s][0] = __ldg(xb + xo[s]);
                xf[s][1] = __ldg(xb + xo[s] + 1);
                xf[s][2] = __ldg(xb + xo[s] + 2);
            }
        }
        __syncthreads();
        cur ^= 1;
    }

    // --- Siamese diff + MLP head, in-block ---
    const float* hf = hbuf + cur * (2 * NBP * 64);
    for (int i = tid; i < NBP * 64; i += BLK) {
        int s = i >> 6, k = i & 63;
        dif[i] = fabsf(hf[s * 64 + k] - hf[(NBP + s) * 64 + k]);
    }
    __syncthreads();

    if (tid < 32) {
        int m = tid;
        float acc[NBP];
        float bb1 = __ldg(b1 + m);
#pragma unroll
        for (int s = 0; s < NBP; s++) acc[s] = bb1;
        for (int k = 0; k < 64; k++) {
            float w = __ldg(W1 + m * 64 + k);
#pragma unroll
            for (int s = 0; s < NBP; s++) acc[s] += w * dif[s * 64 + k];
        }
#pragma unroll
        for (int s = 0; s < NBP; s++) hid[m * NBP + s] = fmaxf(acc[s], 0.0f);
    }
    __syncthreads();

    if (tid < NBP) {
        int gb = bb + tid;
        if (gb < BQ) {
            float a = __ldg(b2);
            for (int m = 0; m < 32; m++)
                a += __ldg(W2 + m) * hid[m * NBP + tid];
            out[gb] = sigf(a);
        }
    }
}

extern "C" void kernel_launch(void* const* d_in, const int* in_sizes, int n_in,
                              void* d_out, int out_size)
{
    const float* x1  = (const float*)d_in[0];
    const float* x2  = (const float*)d_in[1];
    const float* Wih = (const float*)d_in[2];
    const float* Whh = (const float*)d_in[3];
    const float* bih = (const float*)d_in[4];
    const float* bhh = (const float*)d_in[5];
    const float* W1  = (const float*)d_in[6];
    const float* b1  = (const float*)d_in[7];
    const float* W2  = (const float*)d_in[8];
    const float* b2  = (const float*)d_in[9];
    float* out = (float*)d_out;

    cudaFuncSetAttribute(siamese_gru_kernel,
                         cudaFuncAttributeMaxDynamicSharedMemorySize, SMEM_BYTES);

    int grid = (BQ + NBP - 1) / NBP;   // 293 blocks, 2/SM, near-balanced
    siamese_gru_kernel<<<grid, BLK, SMEM_BYTES>>>(
        x1, x2, Wih, Whh, bih, bhh, W1, b1, W2, b2, out);
}